// round 7
// baseline (speedup 1.0000x reference)
#include <cuda_runtime.h>
#include <cuda_fp16.h>
#include <cstdint>

// Problem constants (fixed by dataset): N=50000 nodes, E=1.6M edges, K=128 feat dim.
#define NODE_CAP 50048
#define EDGE_CAP 1700000
#define KDIM 128

// Scratch (no cudaMalloc allowed).
__device__ __align__(16) float  g_bufB[NODE_CAP * KDIM];  // gathered layer-1 (128-dim fp32)
__device__ __align__(16) __half g_h1[NODE_CAP * KDIM];    // layer-1 pre-agg features (fp16)
__device__ __align__(16) __half g_h2[NODE_CAP * 64];      // layer-2 pre-agg features (fp16)
__device__ __align__(16) float  g_W2f[KDIM * 64];         // W2 @ Wf
__device__ __align__(16) float  g_c2[64];                 // b2 @ Wf + bf
__device__ int   g_degO[NODE_CAP];
__device__ int   g_degI[NODE_CAP];
__device__ float g_sO[NODE_CAP];
__device__ float g_sI[NODE_CAP];
__device__ int   g_rowptr[NODE_CAP + 1];
__device__ int   g_cursor[NODE_CAP];
__device__ int   g_csr[EDGE_CAP];        // src indices grouped by dst

// ---------------------------------------------------------------------------
// Degree count, 2 edges per thread (pipeline the L2 atomics).
// ---------------------------------------------------------------------------
__global__ void deg_kernel(const int* __restrict__ src, const int* __restrict__ dst, int E) {
    int i = (blockIdx.x * blockDim.x + threadIdx.x) * 2;
    if (i < E) {
        int s0 = src[i], d0 = dst[i];
        if (i + 1 < E) {
            int s1 = src[i + 1], d1 = dst[i + 1];
            atomicAdd(&g_degO[s0], 1);
            atomicAdd(&g_degO[s1], 1);
            atomicAdd(&g_degI[d0], 1);
            atomicAdd(&g_degI[d1], 1);
        } else {
            atomicAdd(&g_degO[s0], 1);
            atomicAdd(&g_degI[d0], 1);
        }
    }
}

// ---------------------------------------------------------------------------
// Single-block prefix scan over deg_in -> row_ptr (exclusive) + cursors,
// with the rsqrt scale computation fused in.
// ---------------------------------------------------------------------------
__global__ void scan_kernel(int n) {
    __shared__ int part[1024];
    int tid = threadIdx.x;
    int CH = (n + 1023) / 1024;
    int beg = tid * CH;
    int sum = 0;
    for (int i = 0; i < CH; i++) {
        int idx = beg + i;
        if (idx < n) sum += g_degI[idx];
    }
    part[tid] = sum;
    __syncthreads();
    for (int off = 1; off < 1024; off <<= 1) {
        int v = (tid >= off) ? part[tid - off] : 0;
        __syncthreads();
        part[tid] += v;
        __syncthreads();
    }
    int run = (tid == 0) ? 0 : part[tid - 1];
    for (int i = 0; i < CH; i++) {
        int idx = beg + i;
        if (idx < n) {
            int d = g_degI[idx];
            g_rowptr[idx] = run;
            g_cursor[idx] = run;
            run += d;
            g_sI[idx] = rsqrtf((float)max(d, 1));
            g_sO[idx] = rsqrtf((float)max(g_degO[idx], 1));
        }
    }
    if (tid == 1023) g_rowptr[n] = part[1023];
}

// Fill CSR, 2 edges per thread.
__global__ void fill_kernel(const int* __restrict__ src, const int* __restrict__ dst, int E) {
    int i = (blockIdx.x * blockDim.x + threadIdx.x) * 2;
    if (i < E) {
        int d0 = dst[i], s0 = src[i];
        if (i + 1 < E) {
            int d1 = dst[i + 1], s1 = src[i + 1];
            int p0 = atomicAdd(&g_cursor[d0], 1);
            int p1 = atomicAdd(&g_cursor[d1], 1);
            g_csr[p0] = s0;
            g_csr[p1] = s1;
        } else {
            int p0 = atomicAdd(&g_cursor[d0], 1);
            g_csr[p0] = s0;
        }
    }
}

// ---------------------------------------------------------------------------
// Weight-fold precompute: W2f = W2 @ Wf  (128x64), c2 = b2 @ Wf + bf (64)
// ---------------------------------------------------------------------------
__global__ void prep_w_kernel(const float* __restrict__ W2, const float* __restrict__ Wf,
                              const float* __restrict__ b2, const float* __restrict__ bf) {
    int idx = blockIdx.x * blockDim.x + threadIdx.x;
    if (idx < KDIM * 64) {
        int i = idx >> 6;
        int j = idx & 63;
        float s = 0.f;
#pragma unroll 8
        for (int k = 0; k < KDIM; k++)
            s += __ldg(&W2[i * KDIM + k]) * __ldg(&Wf[k * 64 + j]);
        g_W2f[idx] = s;
    }
    if (blockIdx.x == 0 && threadIdx.x < 64) {
        int j = threadIdx.x;
        float s = __ldg(&bf[j]);
#pragma unroll 8
        for (int k = 0; k < KDIM; k++)
            s += __ldg(&b2[k]) * __ldg(&Wf[k * 64 + j]);
        g_c2[j] = s;
    }
}

// ---------------------------------------------------------------------------
// Pull aggregation, fp16 input, 128-dim rows. Warp per dst node; lane l owns
// halfs [4l, 4l+4). Accumulate fp32, store float4.
// ---------------------------------------------------------------------------
__global__ void gather128h_kernel(const uint2* __restrict__ H, float4* __restrict__ Out, int n) {
    int gt = blockIdx.x * blockDim.x + threadIdx.x;
    int w = gt >> 5;
    int l = gt & 31;
    if (w >= n) return;
    int beg = g_rowptr[w];
    int end = g_rowptr[w + 1];
    float4 acc = make_float4(0.f, 0.f, 0.f, 0.f);
    for (int base = beg; base < end; base += 32) {
        int e = base + l;
        int myidx = (e < end) ? __ldg(&g_csr[e]) : 0;
        int cnt = min(32, end - base);
        for (int j = 0; j < cnt; j++) {
            int s = __shfl_sync(0xffffffffu, myidx, j);
            uint2 q = __ldg(&H[s * 32 + l]);
            float2 f0 = __half22float2(*(__half2*)&q.x);
            float2 f1 = __half22float2(*(__half2*)&q.y);
            acc.x += f0.x; acc.y += f0.y; acc.z += f1.x; acc.w += f1.y;
        }
    }
    Out[w * 32 + l] = acc;
}

// ---------------------------------------------------------------------------
// Pull aggregation, fp16 input, 64-dim rows, with the final epilogue fused:
// out[r][c] = (sum_{s in N_in(r)} h2[s][c]) * sI[r] + c2[c]
// ---------------------------------------------------------------------------
__global__ void gather64h_kernel(const __half2* __restrict__ H, float2* __restrict__ Out, int n) {
    int gt = blockIdx.x * blockDim.x + threadIdx.x;
    int w = gt >> 5;
    int l = gt & 31;
    if (w >= n) return;
    int beg = g_rowptr[w];
    int end = g_rowptr[w + 1];
    float2 acc = make_float2(0.f, 0.f);
    for (int base = beg; base < end; base += 32) {
        int e = base + l;
        int myidx = (e < end) ? __ldg(&g_csr[e]) : 0;
        int cnt = min(32, end - base);
        for (int j = 0; j < cnt; j++) {
            int s = __shfl_sync(0xffffffffu, myidx, j);
            float2 f = __half22float2(__ldg(&H[s * 32 + l]));
            acc.x += f.x; acc.y += f.y;
        }
    }
    float si = g_sI[w];
    float2 b = *(const float2*)&g_c2[l * 2];
    Out[w * 32 + l] = make_float2(acc.x * si + b.x, acc.y * si + b.y);
}

// ---------------------------------------------------------------------------
// HMMA GEMM: Ch[M,N] (fp16) = f(A[M,128]) @ W[128,N]
//   MODE 0: a = A[r][k] * s_out[r]
//   MODE 1: a = max(A[r][k]*s_in[r] + bias_in[k], 0) * s_out[r]
// 128 threads = 4 warps. Block tile: BM=64 rows x full N. Warp = 16 rows x N.
// A (fp16) and W^T (fp16) staged in smem with 136-half padded row stride ->
// all mma fragment loads are single conflict-free 4B LDS.
// mma.sync.m16n8k16.row.col.f32.f16.f16.f32.
// ---------------------------------------------------------------------------
template <int N, int MODE>
__global__ void hgemm_kernel(const float* __restrict__ A_src, const float* __restrict__ W,
                             const float* __restrict__ bias_in,
                             __half* __restrict__ Outh, int M) {
    constexpr int BM = 64;
    constexpr int STR = 136;     // padded halfs per row (136*2B: +4 banks/row shift)
    extern __shared__ __half sm[];
    __half* As = sm;             // BM * STR
    __half* Wt = sm + BM * STR;  // N  * STR  (transposed: [n][k])

    int tid = threadIdx.x;       // 128
    int m0 = blockIdx.x * BM;

    // Stage W transposed: coalesced float4 gmem reads, 2B smem scatter (one-time).
    for (int i = tid; i < KDIM * (N / 4); i += 128) {
        int k = i / (N / 4);
        int nc = (i % (N / 4)) * 4;
        float4 wv = *(const float4*)&W[k * N + nc];
        Wt[(nc + 0) * STR + k] = __float2half(wv.x);
        Wt[(nc + 1) * STR + k] = __float2half(wv.y);
        Wt[(nc + 2) * STR + k] = __float2half(wv.z);
        Wt[(nc + 3) * STR + k] = __float2half(wv.w);
    }

    // Stage A tile with fused prologue transform, fp32 -> fp16.
    for (int i = tid; i < BM * KDIM / 4; i += 128) {
        int r = i >> 5;
        int kc = (i & 31) * 4;
        int gr = m0 + r;
        float4 v = make_float4(0.f, 0.f, 0.f, 0.f);
        if (gr < M) {
            v = *(const float4*)&A_src[gr * KDIM + kc];
            if (MODE == 0) {
                float so = g_sO[gr];
                v.x *= so; v.y *= so; v.z *= so; v.w *= so;
            } else {
                float si = g_sI[gr], so = g_sO[gr];
                float4 b = *(const float4*)&bias_in[kc];
                v.x = fmaxf(v.x * si + b.x, 0.f) * so;
                v.y = fmaxf(v.y * si + b.y, 0.f) * so;
                v.z = fmaxf(v.z * si + b.z, 0.f) * so;
                v.w = fmaxf(v.w * si + b.w, 0.f) * so;
            }
        }
        *(__half2*)&As[r * STR + kc]     = __floats2half2_rn(v.x, v.y);
        *(__half2*)&As[r * STR + kc + 2] = __floats2half2_rn(v.z, v.w);
    }
    __syncthreads();

    int w = tid >> 5;
    int t = tid & 31;
    int g = t >> 2;          // group 0..7
    int tg = t & 3;          // thread-in-group 0..3
    int wr = w * 16;         // warp row base within tile

    constexpr int NT = N / 8;
    float c[NT][4];
#pragma unroll
    for (int nt = 0; nt < NT; nt++) {
        c[nt][0] = 0.f; c[nt][1] = 0.f; c[nt][2] = 0.f; c[nt][3] = 0.f;
    }

    const __half* Ar0 = &As[(wr + g) * STR + tg * 2];
    const __half* Ar1 = Ar0 + 8 * STR;

#pragma unroll
    for (int ks = 0; ks < KDIM / 16; ks++) {
        int k0 = ks * 16;
        uint32_t a0 = *(const uint32_t*)&Ar0[k0];
        uint32_t a1 = *(const uint32_t*)&Ar1[k0];
        uint32_t a2 = *(const uint32_t*)&Ar0[k0 + 8];
        uint32_t a3 = *(const uint32_t*)&Ar1[k0 + 8];
#pragma unroll
        for (int nt = 0; nt < NT; nt++) {
            const __half* Bp = &Wt[(nt * 8 + g) * STR + k0 + tg * 2];
            uint32_t b0 = *(const uint32_t*)&Bp[0];
            uint32_t b1 = *(const uint32_t*)&Bp[8];
            asm volatile(
                "mma.sync.aligned.m16n8k16.row.col.f32.f16.f16.f32 "
                "{%0,%1,%2,%3}, {%4,%5,%6,%7}, {%8,%9}, {%0,%1,%2,%3};"
                : "+f"(c[nt][0]), "+f"(c[nt][1]), "+f"(c[nt][2]), "+f"(c[nt][3])
                : "r"(a0), "r"(a1), "r"(a2), "r"(a3), "r"(b0), "r"(b1));
        }
    }

    // Epilogue: pack fp32 accums to fp16, 4B stores.
    int r0 = m0 + wr + g;
#pragma unroll
    for (int nt = 0; nt < NT; nt++) {
        int col = nt * 8 + tg * 2;
        if (r0 < M)
            *(__half2*)&Outh[r0 * N + col] = __floats2half2_rn(c[nt][0], c[nt][1]);
        if (r0 + 8 < M)
            *(__half2*)&Outh[(r0 + 8) * N + col] = __floats2half2_rn(c[nt][2], c[nt][3]);
    }
}

// ---------------------------------------------------------------------------
extern "C" void kernel_launch(void* const* d_in, const int* in_sizes, int n_in,
                              void* d_out, int out_size) {
    const float* X  = (const float*)d_in[0];
    const int* src  = (const int*)d_in[1];
    const int* dst  = (const int*)d_in[2];
    const float* W1 = (const float*)d_in[3];
    const float* b1 = (const float*)d_in[4];
    const float* W2 = (const float*)d_in[5];
    const float* b2 = (const float*)d_in[6];
    const float* Wf = (const float*)d_in[7];
    const float* bf = (const float*)d_in[8];
    float* out = (float*)d_out;

    int n = in_sizes[0] / KDIM;   // 50000
    int E = in_sizes[1];          // 1600000

    void *pB_, *pH1_, *pH2_, *pW2f_, *pDO_, *pDI_;
    cudaGetSymbolAddress(&pB_, g_bufB);
    cudaGetSymbolAddress(&pH1_, g_h1);
    cudaGetSymbolAddress(&pH2_, g_h2);
    cudaGetSymbolAddress(&pW2f_, g_W2f);
    cudaGetSymbolAddress(&pDO_, g_degO);
    cudaGetSymbolAddress(&pDI_, g_degI);

    const int smem128 = (64 + 128) * 136 * (int)sizeof(__half); // 52224 B
    const int smem64  = (64 + 64)  * 136 * (int)sizeof(__half); // 34816 B
    cudaFuncSetAttribute(hgemm_kernel<128, 0>, cudaFuncAttributeMaxDynamicSharedMemorySize, smem128);
    cudaFuncSetAttribute(hgemm_kernel<64, 1>,  cudaFuncAttributeMaxDynamicSharedMemorySize, smem64);

    int gemm_blocks = (n + 63) / 64;
    int agg_blocks  = (n * 32 + 255) / 256;
    int epair_blocks = ((E + 1) / 2 + 255) / 256;

    // 1. degrees -> CSR (by dst) + scales; fold Wf into W2.
    cudaMemsetAsync(pDO_, 0, n * sizeof(int));
    cudaMemsetAsync(pDI_, 0, n * sizeof(int));
    deg_kernel<<<epair_blocks, 256>>>(src, dst, E);
    prep_w_kernel<<<(KDIM * 64 + 255) / 256, 256>>>(W2, Wf, b2, bf);
    scan_kernel<<<1, 1024>>>(n);
    fill_kernel<<<epair_blocks, 256>>>(src, dst, E);

    // 2. layer 1 GEMM (HMMA): h1 (fp16) = (X * s_out) @ W1
    hgemm_kernel<128, 0><<<gemm_blocks, 128, smem128>>>(X, W1, nullptr, (__half*)pH1_, n);

    // 3. aggregate (pull, fp16 in): B = agg(h1)
    gather128h_kernel<<<agg_blocks, 256>>>((const uint2*)pH1_, (float4*)pB_, n);

    // 4. layer 2 + final fold GEMM (HMMA): h2 (fp16) = (relu(B*s_in + b1) * s_out) @ (W2@Wf)
    hgemm_kernel<64, 1><<<gemm_blocks, 128, smem64>>>((const float*)pB_, (const float*)pW2f_,
                                                      b1, (__half*)pH2_, n);

    // 5. aggregate (pull, fp16 in, 64-dim) + fused epilogue -> out
    gather64h_kernel<<<agg_blocks, 256>>>((const __half2*)pH2_, (float2*)out, n);
}

// round 9
// speedup vs baseline: 1.2321x; 1.2321x over previous
#include <cuda_runtime.h>
#include <cuda_fp16.h>
#include <cstdint>

// Problem constants (fixed by dataset): N=50000 nodes, E=1.6M edges, K=128 feat dim.
#define NODE_CAP 50048
#define EDGE_CAP 1700000
#define KDIM 128

// Scratch (no cudaMalloc allowed).
__device__ __align__(16) float  g_bufB[NODE_CAP * KDIM];  // gathered layer-1 (128-dim fp32)
__device__ __align__(16) __half g_h1[NODE_CAP * KDIM];    // layer-1 pre-agg features (fp16), NO sO
__device__ __align__(16) __half g_h2[NODE_CAP * 64];      // layer-2 pre-agg features (fp16), NO sO
__device__ __align__(16) float  g_W2f[KDIM * 64];         // W2 @ Wf
__device__ __align__(16) float  g_c2[64];                 // b2 @ Wf + bf
__device__ int   g_degO[NODE_CAP];
__device__ int   g_degI[NODE_CAP];
__device__ float g_sO[NODE_CAP];
__device__ float g_sI[NODE_CAP];
__device__ int   g_rowptr[NODE_CAP + 1];
__device__ int   g_cursor[NODE_CAP];
__device__ int   g_csr[EDGE_CAP];        // src indices grouped by dst

// ---------------------------------------------------------------------------
// Single-block prefix scan over deg_in -> row_ptr (exclusive) + cursors.
// (degI is L1-resident for the 2nd pass: 200KB on one SM's 228KB L1.)
// ---------------------------------------------------------------------------
__global__ void scan_kernel(int n) {
    __shared__ int part[1024];
    int tid = threadIdx.x;
    int CH = (n + 1023) / 1024;
    int beg = tid * CH;
    int sum = 0;
#pragma unroll 4
    for (int i = 0; i < CH; i++) {
        int idx = beg + i;
        if (idx < n) sum += g_degI[idx];
    }
    part[tid] = sum;
    __syncthreads();
    for (int off = 1; off < 1024; off <<= 1) {
        int v = (tid >= off) ? part[tid - off] : 0;
        __syncthreads();
        part[tid] += v;
        __syncthreads();
    }
    int run = (tid == 0) ? 0 : part[tid - 1];
#pragma unroll 4
    for (int i = 0; i < CH; i++) {
        int idx = beg + i;
        if (idx < n) {
            g_rowptr[idx] = run;
            g_cursor[idx] = run;
            run += g_degI[idx];
        }
    }
    if (tid == 1023) g_rowptr[n] = part[1023];
}

// ---------------------------------------------------------------------------
// Fill CSR (all blocks, 2 edges/thread) + fused side jobs in low blocks:
//   blocks [0,32):  W2f = W2 @ Wf  (128x64, one element/thread)
//   block  32:      c2 = b2 @ Wf + bf
//   blocks [33,33+ceil(n/256)): s_I / s_O rsqrt scales
// Fill is ATOMG-latency / L2-sector bound (issue ~3%), so the extra arithmetic
// in a few blocks rides along for free.
// ---------------------------------------------------------------------------
__global__ void fill_kernel(const int* __restrict__ src, const int* __restrict__ dst,
                            const float* __restrict__ W2, const float* __restrict__ Wf,
                            const float* __restrict__ b2, const float* __restrict__ bf,
                            int E, int n) {
    int b = blockIdx.x;
    int tid = threadIdx.x;

    // CSR fill: 2 edges per thread
    int i = (b * 256 + tid) * 2;
    if (i < E) {
        int d0 = dst[i], s0 = src[i];
        if (i + 1 < E) {
            int d1 = dst[i + 1], s1 = src[i + 1];
            int p0 = atomicAdd(&g_cursor[d0], 1);
            int p1 = atomicAdd(&g_cursor[d1], 1);
            g_csr[p0] = s0;
            g_csr[p1] = s1;
        } else {
            int p0 = atomicAdd(&g_cursor[d0], 1);
            g_csr[p0] = s0;
        }
    }

    if (b < 32) {                       // W2f
        int idx = b * 256 + tid;        // < 8192 = 128*64
        int r = idx >> 6;
        int c = idx & 63;
        float s = 0.f;
#pragma unroll 8
        for (int k = 0; k < KDIM; k++)
            s += __ldg(&W2[r * KDIM + k]) * __ldg(&Wf[k * 64 + c]);
        g_W2f[idx] = s;
    } else if (b == 32) {               // c2
        if (tid < 64) {
            float s = __ldg(&bf[tid]);
#pragma unroll 8
            for (int k = 0; k < KDIM; k++)
                s += __ldg(&b2[k]) * __ldg(&Wf[k * 64 + tid]);
            g_c2[tid] = s;
        }
    } else {                            // scales
        int idx = (b - 33) * 256 + tid;
        if (idx < n) {
            g_sI[idx] = rsqrtf((float)max(g_degI[idx], 1));
            g_sO[idx] = rsqrtf((float)max(g_degO[idx], 1));
        }
    }
}

// ---------------------------------------------------------------------------
// Pull aggregation, fp16 input, 128-dim rows, with s_O[src] applied here:
//   B[w] = sum_{s in N_in(w)} sO[s] * h1[s]
// Warp per dst node; lane l owns halfs [4l,4l+4). Uniform-address csr/sO loads
// (warp broadcast, no shfl chain), unroll-2 for MLP. fp32 accumulate.
// ---------------------------------------------------------------------------
__global__ void gather128h_kernel(const uint2* __restrict__ H, float4* __restrict__ Out, int n) {
    int gt = blockIdx.x * blockDim.x + threadIdx.x;
    int w = gt >> 5;
    int l = gt & 31;
    if (w >= n) return;
    int j = g_rowptr[w];
    int end = g_rowptr[w + 1];
    float4 a0 = make_float4(0.f, 0.f, 0.f, 0.f);
    float4 a1 = make_float4(0.f, 0.f, 0.f, 0.f);
    for (; j + 2 <= end; j += 2) {
        int s0 = __ldg(&g_csr[j]);
        int s1 = __ldg(&g_csr[j + 1]);
        float c0 = __ldg(&g_sO[s0]);
        float c1 = __ldg(&g_sO[s1]);
        uint2 q0 = __ldg(&H[s0 * 32 + l]);
        uint2 q1 = __ldg(&H[s1 * 32 + l]);
        float2 x0 = __half22float2(*(__half2*)&q0.x);
        float2 y0 = __half22float2(*(__half2*)&q0.y);
        float2 x1 = __half22float2(*(__half2*)&q1.x);
        float2 y1 = __half22float2(*(__half2*)&q1.y);
        a0.x += c0 * x0.x; a0.y += c0 * x0.y; a0.z += c0 * y0.x; a0.w += c0 * y0.y;
        a1.x += c1 * x1.x; a1.y += c1 * x1.y; a1.z += c1 * y1.x; a1.w += c1 * y1.y;
    }
    if (j < end) {
        int s0 = __ldg(&g_csr[j]);
        float c0 = __ldg(&g_sO[s0]);
        uint2 q0 = __ldg(&H[s0 * 32 + l]);
        float2 x0 = __half22float2(*(__half2*)&q0.x);
        float2 y0 = __half22float2(*(__half2*)&q0.y);
        a0.x += c0 * x0.x; a0.y += c0 * x0.y; a0.z += c0 * y0.x; a0.w += c0 * y0.y;
    }
    Out[w * 32 + l] = make_float4(a0.x + a1.x, a0.y + a1.y, a0.z + a1.z, a0.w + a1.w);
}

// ---------------------------------------------------------------------------
// Pull aggregation, fp16 input, 64-dim rows, s_O[src] applied, final epilogue
// fused:  out[w][c] = (sum sO[s]*h2[s][c]) * sI[w] + c2[c]
// ---------------------------------------------------------------------------
__global__ void gather64h_kernel(const __half2* __restrict__ H, float2* __restrict__ Out, int n) {
    int gt = blockIdx.x * blockDim.x + threadIdx.x;
    int w = gt >> 5;
    int l = gt & 31;
    if (w >= n) return;
    int j = g_rowptr[w];
    int end = g_rowptr[w + 1];
    float2 a0 = make_float2(0.f, 0.f);
    float2 a1 = make_float2(0.f, 0.f);
    for (; j + 2 <= end; j += 2) {
        int s0 = __ldg(&g_csr[j]);
        int s1 = __ldg(&g_csr[j + 1]);
        float c0 = __ldg(&g_sO[s0]);
        float c1 = __ldg(&g_sO[s1]);
        float2 f0 = __half22float2(__ldg(&H[s0 * 32 + l]));
        float2 f1 = __half22float2(__ldg(&H[s1 * 32 + l]));
        a0.x += c0 * f0.x; a0.y += c0 * f0.y;
        a1.x += c1 * f1.x; a1.y += c1 * f1.y;
    }
    if (j < end) {
        int s0 = __ldg(&g_csr[j]);
        float c0 = __ldg(&g_sO[s0]);
        float2 f0 = __half22float2(__ldg(&H[s0 * 32 + l]));
        a0.x += c0 * f0.x; a0.y += c0 * f0.y;
    }
    float si = g_sI[w];
    float2 b = *(const float2*)&g_c2[l * 2];
    Out[w * 32 + l] = make_float2((a0.x + a1.x) * si + b.x, (a0.y + a1.y) * si + b.y);
}

// ---------------------------------------------------------------------------
// fp32 register-tiled GEMM (proven config): Ch[M,N] (fp16) = f(A[M,128]) @ W[128,N]
//   MODE 0: a = A[r][k]                           (plain; sO moved to gather)
//   MODE 1: a = max(A[r][k]*s_in[r] + bias[k], 0) (layer-1 epilogue fused)
// DEG=true additionally counts edge degrees with fire-and-forget REDs at the
// top (no result -> no scoreboard stall; latency hidden under the GEMM).
// BM=64 rows/block, 256 threads, W + A-tile staged in dynamic smem.
// ---------------------------------------------------------------------------
template <int N, int MODE, bool DEG>
__global__ void gemm_kernel(const float* __restrict__ A_src, const float* __restrict__ W,
                            const float* __restrict__ bias_in,
                            __half* __restrict__ Outh, int M,
                            const int* __restrict__ src, const int* __restrict__ dst, int E) {
    constexpr int BM = 64;
    extern __shared__ float smem[];
    float* Ws = smem;            // K * N
    float* As = smem + KDIM * N; // BM * K

    int tid = threadIdx.x;
    int m0 = blockIdx.x * BM;

    if (DEG) {
        int gid = blockIdx.x * blockDim.x + tid;
        int stride = gridDim.x * blockDim.x;
        for (int e = gid; e < E; e += stride) {
            atomicAdd(&g_degO[src[e]], 1);   // RED: no return value used
            atomicAdd(&g_degI[dst[e]], 1);
        }
    }

    for (int i = tid * 4; i < KDIM * N; i += 256 * 4) {
        *(float4*)&Ws[i] = *(const float4*)&W[i];
    }

    for (int i = tid; i < BM * KDIM / 4; i += 256) {
        int r = i >> 5;
        int kc = (i & 31) * 4;
        int gr = m0 + r;
        float4 v = make_float4(0.f, 0.f, 0.f, 0.f);
        if (gr < M) {
            v = *(const float4*)&A_src[gr * KDIM + kc];
            if (MODE == 1) {
                float si = g_sI[gr];
                float4 b = *(const float4*)&bias_in[kc];
                v.x = fmaxf(v.x * si + b.x, 0.f);
                v.y = fmaxf(v.y * si + b.y, 0.f);
                v.z = fmaxf(v.z * si + b.z, 0.f);
                v.w = fmaxf(v.w * si + b.w, 0.f);
            }
        }
        *(float4*)&As[r * KDIM + kc] = v;
    }
    __syncthreads();

    constexpr int CT = N / 4;        // 32 (N=128) or 16 (N=64)
    constexpr int RT = 256 / CT;     // 8 or 16
    constexpr int RPT = BM / RT;     // 8 or 4
    int ct = tid % CT;
    int rt = tid / CT;
    int c0 = ct * 4;
    int r0 = rt * RPT;

    float4 acc[RPT];
#pragma unroll
    for (int i = 0; i < RPT; i++) acc[i] = make_float4(0.f, 0.f, 0.f, 0.f);

#pragma unroll 4
    for (int k = 0; k < KDIM; k++) {
        float4 b = *(const float4*)&Ws[k * N + c0];
#pragma unroll
        for (int i = 0; i < RPT; i++) {
            float a = As[(r0 + i) * KDIM + k];
            acc[i].x += a * b.x;
            acc[i].y += a * b.y;
            acc[i].z += a * b.z;
            acc[i].w += a * b.w;
        }
    }

#pragma unroll
    for (int i = 0; i < RPT; i++) {
        int gr = m0 + r0 + i;
        if (gr < M) {
            float4 o = acc[i];
            __half2 lo = __floats2half2_rn(o.x, o.y);
            __half2 hi = __floats2half2_rn(o.z, o.w);
            uint2 u;
            u.x = *(unsigned*)&lo;
            u.y = *(unsigned*)&hi;
            *(uint2*)&Outh[gr * N + c0] = u;
        }
    }
}

// ---------------------------------------------------------------------------
extern "C" void kernel_launch(void* const* d_in, const int* in_sizes, int n_in,
                              void* d_out, int out_size) {
    const float* X  = (const float*)d_in[0];
    const int* src  = (const int*)d_in[1];
    const int* dst  = (const int*)d_in[2];
    const float* W1 = (const float*)d_in[3];
    const float* b1 = (const float*)d_in[4];
    const float* W2 = (const float*)d_in[5];
    const float* b2 = (const float*)d_in[6];
    const float* Wf = (const float*)d_in[7];
    const float* bf = (const float*)d_in[8];
    float* out = (float*)d_out;

    int n = in_sizes[0] / KDIM;   // 50000
    int E = in_sizes[1];          // 1600000

    void *pB_, *pH1_, *pH2_, *pW2f_, *pDO_, *pDI_;
    cudaGetSymbolAddress(&pB_, g_bufB);
    cudaGetSymbolAddress(&pH1_, g_h1);
    cudaGetSymbolAddress(&pH2_, g_h2);
    cudaGetSymbolAddress(&pW2f_, g_W2f);
    cudaGetSymbolAddress(&pDO_, g_degO);
    cudaGetSymbolAddress(&pDI_, g_degI);

    const int smem128 = (KDIM * 128 + 64 * KDIM) * sizeof(float); // 96KB
    const int smem64  = (KDIM * 64  + 64 * KDIM) * sizeof(float); // 64KB
    cudaFuncSetAttribute(gemm_kernel<128, 0, true>, cudaFuncAttributeMaxDynamicSharedMemorySize, smem128);
    cudaFuncSetAttribute(gemm_kernel<64, 1, false>, cudaFuncAttributeMaxDynamicSharedMemorySize, smem64);

    int gemm_blocks  = (n + 63) / 64;                 // 782
    int agg_blocks   = (n * 32 + 255) / 256;          // 6250
    int fill_blocks  = ((E + 1) / 2 + 255) / 256;     // 3125 (>= 33 + 196 side-job blocks)

    // 1. zero degree counters
    cudaMemsetAsync(pDO_, 0, n * sizeof(int));
    cudaMemsetAsync(pDI_, 0, n * sizeof(int));

    // 2. layer-1 GEMM (plain X@W1 -> fp16) with degree atomics hidden inside
    gemm_kernel<128, 0, true><<<gemm_blocks, 256, smem128>>>(
        X, W1, nullptr, (__half*)pH1_, n, src, dst, E);

    // 3. rowptr scan, then CSR fill (+ fused W2f/c2/scales side jobs)
    scan_kernel<<<1, 1024>>>(n);
    fill_kernel<<<fill_blocks, 256>>>(src, dst, W2, Wf, b2, bf, E, n);

    // 4. aggregate layer 1 (applies sO[src]): B = sum sO[s]*h1[s]
    gather128h_kernel<<<agg_blocks, 256>>>((const uint2*)pH1_, (float4*)pB_, n);

    // 5. layer-2 GEMM: h2 = relu(B*sI + b1) @ (W2@Wf) -> fp16
    gemm_kernel<64, 1, false><<<gemm_blocks, 256, smem64>>>(
        (const float*)pB_, (const float*)pW2f_, b1, (__half*)pH2_, n,
        nullptr, nullptr, 0);

    // 6. aggregate layer 2 (applies sO[src]) + final epilogue -> out
    gather64h_kernel<<<agg_blocks, 256>>>((const __half2*)pH2_, (float2*)out, n);
}